// round 5
// baseline (speedup 1.0000x reference)
#include <cuda_runtime.h>
#include <math.h>

#define DIM   1024
#define NC    8
#define NPER  4096
#define QDIM  128
#define TOPK  128

// Scratch (no allocations allowed -> __device__ globals)
__device__ float g_w[NC][DIM];                   // q_w^T @ qk per cluster
__device__ float g_b0[NC];                       // q_b . qk
__device__ unsigned long long g_keys[NC][NPER];  // (desc-map(score)<<32)|idx
__device__ int   g_topidx[NC][TOPK];             // sorted top-k indices
__device__ float g_gvec[NC][DIM];                // sum_n e^{s_n} feats[n]
__device__ float g_Z[NC];                        // sum_n e^{s_n}

// ---------------------------------------------------------------------------
// Kernel A: per-cluster qk = key@q_w^T + q_b ; w = q_w^T @ qk ; b0 = q_b.qk
// Also zeroes g_gvec / g_Z. grid = NC, block = 1024.
// ---------------------------------------------------------------------------
__global__ __launch_bounds__(1024) void prep_kernel(const float* __restrict__ key_feats,
                                                    const float* __restrict__ q_w,
                                                    const float* __restrict__ q_b) {
    __shared__ __align__(16) float s_qk[QDIM];
    __shared__ float red[4];
    int c = blockIdx.x;
    int t = threadIdx.x;
    int warp = t >> 5, lane = t & 31;

    g_gvec[c][t] = 0.f;          // t covers all DIM=1024
    if (t == 0) g_Z[c] = 0.f;

    // qk[q] via warp-per-row dots (32 warps x 4 rounds = 128 rows)
    const float4* kr = (const float4*)(key_feats + (size_t)c * DIM);
    #pragma unroll
    for (int rr = 0; rr < 4; rr++) {
        int q = warp + rr * 32;
        const float4* qr = (const float4*)(q_w + (size_t)q * DIM);
        float a = 0.f;
        #pragma unroll
        for (int k = 0; k < 8; k++) {
            float4 x = qr[lane + k * 32], y = kr[lane + k * 32];
            a += x.x * y.x + x.y * y.y + x.z * y.z + x.w * y.w;
        }
        #pragma unroll
        for (int o = 16; o > 0; o >>= 1)
            a += __shfl_xor_sync(0xffffffffu, a, o);
        if (lane == 0) s_qk[q] = a + q_b[q];
    }
    __syncthreads();

    // w[t] = sum_q qk[q] * q_w[q][t]  (coalesced across t)
    float wacc = 0.f;
    #pragma unroll 16
    for (int q = 0; q < QDIM; q++)
        wacc += s_qk[q] * q_w[(size_t)q * DIM + t];
    g_w[c][t] = wacc;

    // b0 = qk . q_b (threads 0..127)
    if (t < QDIM) {
        float p = s_qk[t] * q_b[t];
        #pragma unroll
        for (int o = 16; o > 0; o >>= 1)
            p += __shfl_xor_sync(0xffffffffu, p, o);
        if (lane == 0) red[warp] = p;
    }
    __syncthreads();
    if (t == 0) g_b0[c] = red[0] + red[1] + red[2] + red[3];
}

// ---------------------------------------------------------------------------
// Kernel B (fused single pass over feats, register-resident rows):
// warp owns a row: loads 8 float4/lane, dot vs w (smem), s -> key (g_keys),
// e = exp(s), acc += e*row (registers). Block-combine + global atomics.
// grid = NC*64 (64 rows/block), block = 256 (8 warps x 8 rows each)
// ---------------------------------------------------------------------------
__global__ __launch_bounds__(256) void fused_pass_kernel(const float* __restrict__ feats) {
    __shared__ __align__(16) float sw[DIM];
    __shared__ __align__(16) float sacc[DIM];
    __shared__ float zsh;

    int bid = blockIdx.x;
    int c = bid >> 6;
    int base = (bid & 63) * 64;
    int t = threadIdx.x, warp = t >> 5, lane = t & 31;

    ((float4*)sw)[t] = ((const float4*)(g_w[c]))[t];
    ((float4*)sacc)[t] = make_float4(0.f, 0.f, 0.f, 0.f);
    if (t == 0) zsh = 0.f;
    float b0 = g_b0[c];
    __syncthreads();

    const float4* fb =
        (const float4*)(feats + ((size_t)c * NPER + base + (size_t)warp * 8) * DIM);

    float4 acc[8];
    #pragma unroll
    for (int k = 0; k < 8; k++) acc[k] = make_float4(0.f, 0.f, 0.f, 0.f);
    float zw = 0.f;

    for (int r = 0; r < 8; r++) {
        float4 f[8];
        #pragma unroll
        for (int k = 0; k < 8; k++)
            f[k] = fb[(size_t)r * 256 + lane + k * 32];

        float d = 0.f;
        #pragma unroll
        for (int k = 0; k < 8; k++) {
            float4 w4 = ((const float4*)sw)[lane + k * 32];
            d += f[k].x * w4.x + f[k].y * w4.y + f[k].z * w4.z + f[k].w * w4.w;
        }
        #pragma unroll
        for (int o = 16; o > 0; o >>= 1)
            d += __shfl_xor_sync(0xffffffffu, d, o);

        float s = (d + b0) * 0.08838834764831845f;  // 1/sqrt(128)
        float e = expf(s);                           // |s| small: safe
        zw += e;

        if (lane == 0) {
            int n = base + warp * 8 + r;
            unsigned u = __float_as_uint(s);
            u = (u & 0x80000000u) ? ~u : (u | 0x80000000u);  // ascending map
            unsigned dm = ~u;                                // descending map
            g_keys[c][n] = ((unsigned long long)dm << 32) | (unsigned)n;
        }

        #pragma unroll
        for (int k = 0; k < 8; k++) {
            acc[k].x += e * f[k].x; acc[k].y += e * f[k].y;
            acc[k].z += e * f[k].z; acc[k].w += e * f[k].w;
        }
    }

    // cross-warp combine (serialized rounds)
    for (int wi = 0; wi < 8; wi++) {
        if (warp == wi) {
            #pragma unroll
            for (int k = 0; k < 8; k++) {
                float4* p = &((float4*)sacc)[lane + k * 32];
                float4 v = *p;
                v.x += acc[k].x; v.y += acc[k].y;
                v.z += acc[k].z; v.w += acc[k].w;
                *p = v;
            }
            if (lane == 0) zsh += zw;
        }
        __syncthreads();
    }

    float4 v = ((float4*)sacc)[t];
    float* gp = g_gvec[c] + t * 4;
    atomicAdd(gp + 0, v.x);
    atomicAdd(gp + 1, v.y);
    atomicAdd(gp + 2, v.z);
    atomicAdd(gp + 3, v.w);
    if (t == 0) atomicAdd(&g_Z[c], zsh);
}

// ---------------------------------------------------------------------------
// Kernel C (merged): blocks 0..NC-1  -> exact top-128 radix select + sort
//                    blocks NC..NC+255 -> fusion matvec
// grid = NC + NC*32 = 264, block = 1024
// ---------------------------------------------------------------------------
__global__ __launch_bounds__(1024) void topk_fusion_kernel(
        const float* __restrict__ v_w,
        const float* __restrict__ v_b,
        float* __restrict__ out) {
    __shared__ __align__(16) float sg[DIM];
    __shared__ unsigned hist[256];
    __shared__ unsigned wsum[8];
    __shared__ unsigned long long s_prefix;
    __shared__ unsigned s_remaining;
    __shared__ unsigned long long winners[TOPK];
    __shared__ unsigned wcnt;

    int t = threadIdx.x;
    int warp = t >> 5, lane = t & 31;

    if (blockIdx.x >= NC) {
        // ---------------- fusion part ----------------
        int bid = blockIdx.x - NC;            // 0..255
        int c = bid >> 5;
        int o0 = (bid & 31) * 32;
        float invZ = 1.f / g_Z[c];
        sg[t] = g_gvec[c][t] * invZ;
        __syncthreads();

        int o = o0 + warp;                    // 32 warps -> 32 outputs
        const float4* vr = (const float4*)(v_w + (size_t)o * DIM);
        const float4* gr = (const float4*)sg;
        float acc = 0.f;
        #pragma unroll
        for (int i = 0; i < 8; i++) {
            int idx = lane + i * 32;
            float4 a = vr[idx], b = gr[idx];
            acc += a.x * b.x + a.y * b.y + a.z * b.z + a.w * b.w;
        }
        #pragma unroll
        for (int ofs = 16; ofs > 0; ofs >>= 1)
            acc += __shfl_xor_sync(0xffffffffu, acc, ofs);
        if (lane == 0)
            out[(size_t)1024 * 1024 + (size_t)c * DIM + o] = acc + v_b[o];
        return;
    }

    // ---------------- topk part ----------------
    int c = blockIdx.x;

    unsigned long long key[4];
    #pragma unroll
    for (int i = 0; i < 4; i++) key[i] = g_keys[c][t + i * 1024];

    unsigned long long prefix = 0ull, mask = 0ull;
    unsigned remaining = TOPK;

    for (int level = 0; level < 8; level++) {
        int shift = 56 - 8 * level;
        if (t < 256) hist[t] = 0u;
        __syncthreads();

        // warp-aggregated histogram (clustered digits -> few atomics)
        #pragma unroll
        for (int i = 0; i < 4; i++) {
            bool active = ((key[i] & mask) == prefix);
            unsigned digit = active
                ? (unsigned)((key[i] >> shift) & 255u)
                : (256u + (unsigned)lane);          // unique -> self group
            unsigned grp = __match_any_sync(0xffffffffu, digit);
            int leader = __ffs(grp) - 1;
            if (active && lane == leader)
                atomicAdd(&hist[digit], (unsigned)__popc(grp));
        }
        __syncthreads();

        // inclusive scan of hist[256] via warps 0..7
        unsigned own = 0u, v = 0u;
        if (t < 256) {
            own = hist[t];
            v = own;
            #pragma unroll
            for (int o = 1; o < 32; o <<= 1) {
                unsigned u = __shfl_up_sync(0xffffffffu, v, o);
                if (lane >= o) v += u;
            }
            if (lane == 31) wsum[warp] = v;
        }
        __syncthreads();
        if (t == 0) {
            unsigned srun = 0u;
            #pragma unroll
            for (int i = 0; i < 8; i++) { unsigned x = wsum[i]; wsum[i] = srun; srun += x; }
        }
        __syncthreads();
        if (t < 256) {
            unsigned incl = v + wsum[warp];
            unsigned excl = incl - own;
            if (own > 0u && excl < remaining && incl >= remaining) {
                s_prefix = prefix | ((unsigned long long)(unsigned)t << shift);
                s_remaining = remaining - excl;
            }
        }
        __syncthreads();
        prefix = s_prefix;
        remaining = s_remaining;
        mask |= (0xffull << shift);
    }

    // prefix == exact 128th-smallest key; winners are keys <= prefix
    if (t == 0) wcnt = 0u;
    __syncthreads();
    #pragma unroll
    for (int i = 0; i < 4; i++) {
        if (key[i] <= prefix) {
            unsigned p = atomicAdd(&wcnt, 1u);
            winners[p] = key[i];
        }
    }
    __syncthreads();

    // bitonic sort 128 winners ascending (desc score, asc idx)
    for (unsigned k = 2; k <= TOPK; k <<= 1) {
        for (unsigned j = k >> 1; j > 0; j >>= 1) {
            if (t < TOPK) {
                unsigned i = (unsigned)t, ixj = i ^ j;
                if (ixj > i) {
                    unsigned long long a = winners[i], b = winners[ixj];
                    bool up = ((i & k) == 0);
                    if ((a > b) == up) { winners[i] = b; winners[ixj] = a; }
                }
            }
            __syncthreads();
        }
    }

    if (t < TOPK)
        g_topidx[c][t] = (int)(unsigned)(winners[t] & 0xffffffffu);
}

// ---------------------------------------------------------------------------
// Kernel D: gather selected rows: out[c*128+k] = feats[c][topidx[c][k]]
// grid = 256 (4 rows/block), block = 256 (64 threads/row, 4 float4/thread)
// ---------------------------------------------------------------------------
__global__ void gather_kernel(const float* __restrict__ feats,
                              float* __restrict__ out) {
    int t = threadIdx.x;
    int row = blockIdx.x * 4 + (t >> 6);
    int c = row >> 7, k = row & 127;
    int src = g_topidx[c][k];
    const float4* s = (const float4*)(feats + ((size_t)c * NPER + src) * DIM);
    float4* dst = (float4*)(out + (size_t)row * DIM);
    int ci = t & 63;
    float4 v0 = s[ci];
    float4 v1 = s[ci + 64];
    float4 v2 = s[ci + 128];
    float4 v3 = s[ci + 192];
    dst[ci] = v0;
    dst[ci + 64] = v1;
    dst[ci + 128] = v2;
    dst[ci + 192] = v3;
}

// ---------------------------------------------------------------------------
extern "C" void kernel_launch(void* const* d_in, const int* in_sizes, int n_in,
                              void* d_out, int out_size) {
    const float* feats     = (const float*)d_in[0];  // [8,4096,1024]
    const float* key_feats = (const float*)d_in[1];  // [8,1,1024]
    const float* q_w       = (const float*)d_in[2];  // [128,1024]
    const float* q_b       = (const float*)d_in[3];  // [128]
    const float* v_w       = (const float*)d_in[4];  // [1024,1024]
    const float* v_b       = (const float*)d_in[5];  // [1024]
    float* out = (float*)d_out;  // selected [1024,1024] then fus [8,1024]

    prep_kernel<<<NC, 1024>>>(key_feats, q_w, q_b);
    fused_pass_kernel<<<NC * 64, 256>>>(feats);
    topk_fusion_kernel<<<NC + NC * 32, 1024>>>(v_w, v_b, out);
    gather_kernel<<<256, 256>>>(feats, out);
}